// round 12
// baseline (speedup 1.0000x reference)
#include <cuda_runtime.h>
#include <cstdint>
#include <math.h>

#define DM   1024
#define NEXP 32
#define FE   128
#define TT   4
#define BATCH 4
#define SEQ  4096
#define NTOK (BATCH*SEQ)   // 16384
#define NGRP (SEQ/TT)      // 1024

typedef unsigned long long ull;

// scratch (device globals; no allocation)
__device__ float g_logitsT[BATCH*TT*NEXP*NGRP];   // 2MB [(b*4+t)*32+e][g]
__device__ int   g_selg[BATCH*TT*NEXP];           // [(b*4+t)*32+e]
__device__ float g_selp[BATCH*TT*NEXP];
__device__ float g_av[NEXP*16*FE];                // [e][b4t][f] up-proj sums
__device__ float g_W[BATCH*NEXP*TT*FE];           // [(b*32+e)*4+t][f]

__device__ __forceinline__ ull pack2(float a, float b) {
    ull r; asm("mov.b64 %0,{%1,%2};" : "=l"(r) : "f"(a), "f"(b)); return r;
}
__device__ __forceinline__ void unpack2(ull v, float& a, float& b) {
    asm("mov.b64 {%0,%1},%2;" : "=f"(a), "=f"(b) : "l"(v));
}
__device__ __forceinline__ void ffma2(ull& d, ull a, ull b) {
    asm("fma.rn.f32x2 %0,%1,%2,%0;" : "+l"(d) : "l"(a), "l"(b));
}

// ---------------------------------------------------------------------------
// K1: zero output + logits GEMM (R7 config, proven 48.7us).
// 128 blocks x 512 threads; warp = (eq, ks); thread tile 4 tok x 8 exp.
// x staged transposed [k][tok] pad-129 (conflict-free STS/LDS).
// ---------------------------------------------------------------------------
#define XKROW 129
#define XKBUF (32*XKROW)
#define SMEM1 (131072 + 2*XKBUF*4)              // 164096

__global__ void __launch_bounds__(512, 1)
k_logits(const float* __restrict__ x, const float* __restrict__ ctrl,
         float* __restrict__ out)
{
    extern __shared__ char smraw[];
    ull*   ctrl_s = reinterpret_cast<ull*>(smraw);              // [1024k][16 ull]
    float* xk0    = reinterpret_cast<float*>(smraw + 131072);   // [32][129]
    float* xk1    = xk0 + XKBUF;

    const int tid = threadIdx.x;
    const int tg  = tid & 31;
    const int w   = tid >> 5;
    const int eq  = w >> 2;
    const int ks  = w & 3;
    const int tb  = blockIdx.x;
    const float* xblk = x + (size_t)tb * 128 * DM;

    // fire-and-forget zero of this block's output slab
    {
        float4 z = make_float4(0.f, 0.f, 0.f, 0.f);
        float4* op = reinterpret_cast<float4*>(out) + (size_t)tb * 32768;
        #pragma unroll
        for (int i = 0; i < 64; i++) op[tid + i*512] = z;
    }

    const int s_tok0 = tid >> 3;
    const int s_kq   = tid & 7;
    const float* sbase  = xblk + (size_t)s_tok0*DM + s_kq*4;
    const float* sbase2 = sbase + (size_t)64*DM;

    float4 r0 = *reinterpret_cast<const float4*>(sbase);
    float4 r1 = *reinterpret_cast<const float4*>(sbase2);

    {
        const float4* cg4 = reinterpret_cast<const float4*>(ctrl);
        float4* cs4 = reinterpret_cast<float4*>(ctrl_s);
        #pragma unroll
        for (int i = 0; i < 16; i++) cs4[tid + i*512] = cg4[tid + i*512];
    }
    {
        const float* p0 = reinterpret_cast<const float*>(&r0);
        const float* p1 = reinterpret_cast<const float*>(&r1);
        #pragma unroll
        for (int j = 0; j < 4; j++) {
            xk0[(s_kq*4 + j)*XKROW + s_tok0]      = p0[j];
            xk0[(s_kq*4 + j)*XKROW + s_tok0 + 64] = p1[j];
        }
    }
    __syncthreads();

    ull acc[4][4];
    #pragma unroll
    for (int i = 0; i < 4; i++)
        #pragma unroll
        for (int p = 0; p < 4; p++) acc[i][p] = 0ull;

    for (int c = 0; c < 32; c++) {
        if (c < 31) {
            r0 = *reinterpret_cast<const float4*>(sbase  + (c+1)*32);
            r1 = *reinterpret_cast<const float4*>(sbase2 + (c+1)*32);
        }
        const float* xb = (c & 1) ? xk1 : xk0;
        #pragma unroll
        for (int u = 0; u < 8; u++) {
            const ulonglong2* cb = reinterpret_cast<const ulonglong2*>(
                ctrl_s + (size_t)(c*32 + ks*8 + u)*16 + eq*4);
            ulonglong2 q0 = cb[0], q1 = cb[1];
            ull cu0 = q0.x, cu1 = q0.y, cu2 = q1.x, cu3 = q1.y;
            const float* xrow = xb + (ks*8 + u)*XKROW + tg;
            #pragma unroll
            for (int i = 0; i < 4; i++) {
                float xf = xrow[32*i];
                ull x2 = pack2(xf, xf);
                ffma2(acc[i][0], x2, cu0);
                ffma2(acc[i][1], x2, cu1);
                ffma2(acc[i][2], x2, cu2);
                ffma2(acc[i][3], x2, cu3);
            }
        }
        if (c < 31) {
            float* bw = ((c+1) & 1) ? xk1 : xk0;
            const float* p0 = reinterpret_cast<const float*>(&r0);
            const float* p1 = reinterpret_cast<const float*>(&r1);
            #pragma unroll
            for (int j = 0; j < 4; j++) {
                bw[(s_kq*4 + j)*XKROW + s_tok0]      = p0[j];
                bw[(s_kq*4 + j)*XKROW + s_tok0 + 64] = p1[j];
            }
        }
        __syncthreads();
    }

    ull* red = ctrl_s;
    #pragma unroll
    for (int i = 0; i < 4; i++)
        #pragma unroll
        for (int p = 0; p < 4; p++)
            red[(((size_t)(eq*4 + ks)*128) + (tg + 32*i))*4 + p] = acc[i][p];
    __syncthreads();

    #pragma unroll
    for (int j = 0; j < 4; j++) {
        int s = tid*4 + j;
        int tok = s >> 4, pr = s & 15;
        int peq = pr >> 2, pp = pr & 3;
        float lo = 0.f, hi = 0.f;
        #pragma unroll
        for (int k2 = 0; k2 < 4; k2++) {
            float a, b;
            unpack2(red[(((size_t)(peq*4 + k2)*128) + tok)*4 + pp], a, b);
            lo += a; hi += b;
        }
        int gt = tb*128 + tok;
        int b  = gt >> 12;
        int sg = gt & 4095;
        int g  = sg >> 2, t = sg & 3;
        float tbk = (float)t * (1e-6f / 3.0f);   // linspace(0,1e-6,4)[t]
        int row = (b*4 + t)*32 + 2*pr;
        g_logitsT[(size_t)row*1024 + g]     = lo + tbk;
        g_logitsT[(size_t)(row+1)*1024 + g] = hi + tbk;
    }
}

// ---------------------------------------------------------------------------
// K_sel: one block per (b,t,e) row: argmax + softmax denom; also zeroes g_av.
// ---------------------------------------------------------------------------
__global__ void __launch_bounds__(256, 8)
k_sel()
{
    __shared__ float rm[8];
    __shared__ int   rmi[8];
    __shared__ float rs[8];
    __shared__ float mfin;

    const int tid  = threadIdx.x;
    const int lane = tid & 31;
    const int wp   = tid >> 5;
    const float* L = g_logitsT + ((size_t)blockIdx.x << 10);

    // zero this row's g_av slot: blockIdx = bt*32 + e -> g_av[e][bt][0..127]
    {
        int e  = blockIdx.x & 31;
        int bt = blockIdx.x >> 5;
        if (tid < 128) g_av[((size_t)e*16 + bt)*FE + tid] = 0.f;
    }

    float m = -3.4e38f; int mi = 0;
    #pragma unroll
    for (int j = 0; j < 4; j++) {
        int i = tid + j*256;
        float v = L[i];
        if (v > m) { m = v; mi = i; }
    }
    #pragma unroll
    for (int o = 16; o; o >>= 1) {
        float om = __shfl_down_sync(0xffffffffu, m, o);
        int   oi = __shfl_down_sync(0xffffffffu, mi, o);
        if (om > m || (om == m && oi < mi)) { m = om; mi = oi; }
    }
    if (lane == 0) { rm[wp] = m; rmi[wp] = mi; }
    __syncthreads();
    if (tid == 0) {
        #pragma unroll
        for (int w = 1; w < 8; w++) {
            if (rm[w] > m || (rm[w] == m && rmi[w] < mi)) { m = rm[w]; mi = rmi[w]; }
        }
        g_selg[blockIdx.x] = mi;
        mfin = m;
    }
    __syncthreads();
    m = mfin;

    float s = 0.f;
    #pragma unroll
    for (int j = 0; j < 4; j++) s += expf(L[tid + j*256] - m);
    #pragma unroll
    for (int o = 16; o; o >>= 1) s += __shfl_down_sync(0xffffffffu, s, o);
    if (lane == 0) rs[wp] = s;
    __syncthreads();
    if (tid == 0) {
        float tot = 0.f;
        #pragma unroll
        for (int w = 0; w < 8; w++) tot += rs[w];
        g_selp[blockIdx.x] = 1.0f / tot;
    }
}

// ---------------------------------------------------------------------------
// K_up: b-merged up-projection. grid 128 = (e, fs, ds), 256 threads.
// Block: expert e, f-range fs*64..+64, d-range ds*512..+512, ALL 16 (b,t).
// f1 read exactly once chip-wide. Partials atomicAdd'd into g_av.
// ---------------------------------------------------------------------------
#define SMEM_UP ((16*512 + 4*16*64) * 4)   // xs 32KB + part 16KB = 49152
__global__ void __launch_bounds__(256, 2)
k_up(const float* __restrict__ x, const float* __restrict__ f1)
{
    extern __shared__ float sm[];
    float* xs   = sm;               // [16][512]
    float* part = sm + 16*512;      // [4 dc][16 r][64 f]
    __shared__ int sgq[16];

    const int tid = threadIdx.x;
    const int e  = blockIdx.x >> 2;
    const int fs = (blockIdx.x >> 1) & 1;
    const int ds = blockIdx.x & 1;

    if (tid < 16) sgq[tid] = g_selg[tid*32 + e];   // tid = b*4+t
    __syncthreads();

    // load 16 selected rows x 512 floats (this block's d-slice)
    #pragma unroll
    for (int i = 0; i < 8; i++) {
        int q = tid + i*256;             // 0..2047 float4 slots
        int r = q >> 7;
        int c4 = q & 127;
        int b = r >> 2, t = r & 3;
        reinterpret_cast<float4*>(xs + r*512)[c4] =
            reinterpret_cast<const float4*>(
                x + ((size_t)b*SEQ + sgq[r]*4 + t)*DM + ds*512)[c4];
    }
    __syncthreads();

    // up-projection: thread = (f, dc); dc covers 128 d
    {
        const int f  = tid & 63;
        const int dc = tid >> 6;
        float acc[16];
        #pragma unroll
        for (int r = 0; r < 16; r++) acc[r] = 0.f;

        const float* f1p = f1 + (size_t)(ds*512 + dc*128)*(NEXP*FE) + e*FE + fs*64 + f;
        const float4* xb4 = reinterpret_cast<const float4*>(xs);

        #pragma unroll 2
        for (int d4 = 0; d4 < 32; d4++) {
            float w0 = f1p[(size_t)(4*d4+0)*(NEXP*FE)];
            float w1 = f1p[(size_t)(4*d4+1)*(NEXP*FE)];
            float w2 = f1p[(size_t)(4*d4+2)*(NEXP*FE)];
            float w3 = f1p[(size_t)(4*d4+3)*(NEXP*FE)];
            #pragma unroll
            for (int r = 0; r < 16; r++) {
                float4 xv = xb4[r*128 + dc*32 + d4];
                acc[r] += xv.x*w0 + xv.y*w1 + xv.z*w2 + xv.w*w3;
            }
        }
        #pragma unroll
        for (int r = 0; r < 16; r++) part[(dc*16 + r)*64 + f] = acc[r];
    }
    __syncthreads();

    // reduce dc and atomicAdd into g_av (2 ds blocks contribute; commutative)
    #pragma unroll
    for (int i = tid; i < 1024; i += 256) {
        int r = i >> 6, ff = i & 63;
        float s = part[(0*16+r)*64+ff] + part[(1*16+r)*64+ff]
                + part[(2*16+r)*64+ff] + part[(3*16+r)*64+ff];
        atomicAdd(&g_av[((size_t)e*16 + r)*FE + fs*64 + ff], s);
    }
}

// ---------------------------------------------------------------------------
// K_W: bias + duplicate-group mixing + relu + p scaling. grid 128 (b,e).
// ---------------------------------------------------------------------------
__global__ void __launch_bounds__(128, 8)
k_W(const float* __restrict__ bias)
{
    const int b = blockIdx.x >> 5, e = blockIdx.x & 31;
    const int f = threadIdx.x;

    float av[4]; int gg[4]; float pp[4];
    #pragma unroll
    for (int t = 0; t < 4; t++) {
        av[t] = g_av[((size_t)e*16 + b*4 + t)*FE + f];
        gg[t] = g_selg[(b*4 + t)*32 + e];
        pp[t] = g_selp[(b*4 + t)*32 + e];
    }
    float bi = bias[e*FE + f];
    #pragma unroll
    for (int t = 0; t < 4; t++) {
        float sum = bi;
        #pragma unroll
        for (int t2 = 0; t2 < 4; t2++)
            if (gg[t2] == gg[t]) sum += pp[t2] * av[t2];
        g_W[((size_t)(b*32 + e)*4 + t)*FE + f] = pp[t] * fmaxf(sum, 0.f);
    }
}

// ---------------------------------------------------------------------------
// K_down: b-merged down-projection + scatter. grid 128 = (e, ds'), 256 thr.
// f2 read exactly once chip-wide. FFMA2 over (b,t)-pairs, W pre-paired.
// ---------------------------------------------------------------------------
__global__ void __launch_bounds__(256, 2)
k_down(const float* __restrict__ f2, float* __restrict__ out)
{
    __shared__ ull Wp[8][128];     // pair p = (bt=2p, bt=2p+1)
    __shared__ int sgq[16];

    const int tid = threadIdx.x;
    const int e  = blockIdx.x >> 2;
    const int ds = blockIdx.x & 3;

    if (tid < 16) sgq[tid] = g_selg[tid*32 + e];
    #pragma unroll
    for (int i = tid; i < 1024; i += 256) {
        int p = i >> 7, ff = i & 127;
        int bt0 = 2*p, bt1 = 2*p + 1;
        float w0 = g_W[((size_t)((bt0 >> 2)*32 + e)*4 + (bt0 & 3))*FE + ff];
        float w1 = g_W[((size_t)((bt1 >> 2)*32 + e)*4 + (bt1 & 3))*FE + ff];
        Wp[p][ff] = pack2(w0, w1);
    }
    __syncthreads();

    const int dp = ds*256 + tid;
    const float* f2p = f2 + (size_t)e*FE*DM + dp;

    ull o[8];
    #pragma unroll
    for (int p = 0; p < 8; p++) o[p] = 0ull;

    #pragma unroll 8
    for (int ff = 0; ff < 128; ff++) {
        float v = f2p[(size_t)ff*DM];
        ull v2 = pack2(v, v);
        #pragma unroll
        for (int p = 0; p < 8; p++) ffma2(o[p], v2, Wp[p][ff]);
    }

    #pragma unroll
    for (int p = 0; p < 8; p++) {
        float lo, hi;
        unpack2(o[p], lo, hi);
        int bt0 = 2*p, bt1 = 2*p + 1;
        atomicAdd(out + ((size_t)(bt0 >> 2)*SEQ + sgq[bt0]*4 + (bt0 & 3))*DM + dp, lo);
        atomicAdd(out + ((size_t)(bt1 >> 2)*SEQ + sgq[bt1]*4 + (bt1 & 3))*DM + dp, hi);
    }
}

extern "C" void kernel_launch(void* const* d_in, const int* in_sizes, int n_in,
                              void* d_out, int out_size)
{
    const float* x    = (const float*)d_in[0];
    const float* ctrl = (const float*)d_in[1];
    const float* f1   = (const float*)d_in[2];
    const float* bias = (const float*)d_in[3];
    const float* f2   = (const float*)d_in[4];
    float* out = (float*)d_out;

    cudaFuncSetAttribute(k_logits, cudaFuncAttributeMaxDynamicSharedMemorySize, SMEM1);
    cudaFuncSetAttribute(k_up, cudaFuncAttributeMaxDynamicSharedMemorySize, SMEM_UP);

    k_logits<<<128, 512, SMEM1>>>(x, ctrl, out);
    k_sel<<<BATCH*TT*NEXP, 256>>>();
    k_up<<<128, 256, SMEM_UP>>>(x, f1);
    k_W<<<BATCH*NEXP, 128>>>(bias);
    k_down<<<128, 256>>>(f2, out);
}

// round 13
// speedup vs baseline: 1.2212x; 1.2212x over previous
#include <cuda_runtime.h>
#include <cstdint>
#include <math.h>

#define DM   1024
#define NEXP 32
#define FE   128
#define TT   4
#define BATCH 4
#define SEQ  4096
#define NTOK (BATCH*SEQ)   // 16384
#define NGRP (SEQ/TT)      // 1024

typedef unsigned long long ull;

// scratch (device globals; no allocation)
__device__ float g_logitsT[BATCH*TT*NEXP*NGRP];   // 2MB [(b*4+t)*32+e][g]
__device__ int   g_selg[BATCH*TT*NEXP];
__device__ float g_selp[BATCH*TT*NEXP];

__device__ __forceinline__ ull pack2(float a, float b) {
    ull r; asm("mov.b64 %0,{%1,%2};" : "=l"(r) : "f"(a), "f"(b)); return r;
}
__device__ __forceinline__ void unpack2(ull v, float& a, float& b) {
    asm("mov.b64 {%0,%1},%2;" : "=f"(a), "=f"(b) : "l"(v));
}
__device__ __forceinline__ void ffma2(ull& d, ull a, ull b) {
    asm("fma.rn.f32x2 %0,%1,%2,%0;" : "+l"(d) : "l"(a), "l"(b));
}

// ---------------------------------------------------------------------------
// K1: zero output + logits GEMM. 128 blocks x 512 threads (R7 layout).
// warp = (eq, ks); thread tile 4 tok x 8 exp; x staged transposed [k][tok]
// pad-129 (conflict-free STS/LDS). NEW: chunk-PAIR pipeline with 4 staging
// buffers -> 16 barriers instead of 32, and LDG->STS slack of a full pair.
// ---------------------------------------------------------------------------
#define XKROW 129
#define XKBUF (32*XKROW)
#define SMEM1 (131072 + 4*XKBUF*4)              // 197120

__device__ __forceinline__ void compute_chunk(
    const float* __restrict__ xb, const ull* __restrict__ ctrl_s,
    int c, int ks, int eq, int tg, ull acc[4][4])
{
    #pragma unroll
    for (int u = 0; u < 8; u++) {
        const ulonglong2* cb = reinterpret_cast<const ulonglong2*>(
            ctrl_s + (size_t)(c*32 + ks*8 + u)*16 + eq*4);
        ulonglong2 q0 = cb[0], q1 = cb[1];
        ull cu0 = q0.x, cu1 = q0.y, cu2 = q1.x, cu3 = q1.y;
        const float* xrow = xb + (ks*8 + u)*XKROW + tg;
        #pragma unroll
        for (int i = 0; i < 4; i++) {
            float xf = xrow[32*i];
            ull x2 = pack2(xf, xf);
            ffma2(acc[i][0], x2, cu0);
            ffma2(acc[i][1], x2, cu1);
            ffma2(acc[i][2], x2, cu2);
            ffma2(acc[i][3], x2, cu3);
        }
    }
}

__global__ void __launch_bounds__(512, 1)
k_logits(const float* __restrict__ x, const float* __restrict__ ctrl,
         float* __restrict__ out)
{
    extern __shared__ char smraw[];
    ull*   ctrl_s = reinterpret_cast<ull*>(smraw);              // [1024k][16 ull]
    float* xk     = reinterpret_cast<float*>(smraw + 131072);   // 4 x [32][129]

    const int tid = threadIdx.x;
    const int tg  = tid & 31;
    const int w   = tid >> 5;
    const int eq  = w >> 2;
    const int ks  = w & 3;
    const int tb  = blockIdx.x;
    const float* xblk = x + (size_t)tb * 128 * DM;

    // fire-and-forget zero of this block's output slab
    {
        float4 z = make_float4(0.f, 0.f, 0.f, 0.f);
        float4* op = reinterpret_cast<float4*>(out) + (size_t)tb * 32768;
        #pragma unroll
        for (int i = 0; i < 64; i++) op[tid + i*512] = z;
    }

    const int s_tok0 = tid >> 3;
    const int s_kq   = tid & 7;
    const float* sbase  = xblk + (size_t)s_tok0*DM + s_kq*4;
    const float* sbase2 = sbase + (size_t)64*DM;

    // prologue: load pair 0 (chunks 0,1)
    float4 ra0 = *reinterpret_cast<const float4*>(sbase);
    float4 ra1 = *reinterpret_cast<const float4*>(sbase2);
    float4 rb0 = *reinterpret_cast<const float4*>(sbase  + 32);
    float4 rb1 = *reinterpret_cast<const float4*>(sbase2 + 32);

    // load full controller into smem
    {
        const float4* cg4 = reinterpret_cast<const float4*>(ctrl);
        float4* cs4 = reinterpret_cast<float4*>(ctrl_s);
        #pragma unroll
        for (int i = 0; i < 16; i++) cs4[tid + i*512] = cg4[tid + i*512];
    }
    // stage pair 0 into set 0 (buffers 0,1)
    {
        const float* pa0 = reinterpret_cast<const float*>(&ra0);
        const float* pa1 = reinterpret_cast<const float*>(&ra1);
        const float* pb0 = reinterpret_cast<const float*>(&rb0);
        const float* pb1 = reinterpret_cast<const float*>(&rb1);
        float* b0 = xk;
        float* b1 = xk + XKBUF;
        #pragma unroll
        for (int j = 0; j < 4; j++) {
            b0[(s_kq*4 + j)*XKROW + s_tok0]      = pa0[j];
            b0[(s_kq*4 + j)*XKROW + s_tok0 + 64] = pa1[j];
            b1[(s_kq*4 + j)*XKROW + s_tok0]      = pb0[j];
            b1[(s_kq*4 + j)*XKROW + s_tok0 + 64] = pb1[j];
        }
    }
    __syncthreads();

    ull acc[4][4];
    #pragma unroll
    for (int i = 0; i < 4; i++)
        #pragma unroll
        for (int p = 0; p < 4; p++) acc[i][p] = 0ull;

    #pragma unroll 2
    for (int p = 0; p < 16; p++) {
        const int s = p & 1;                  // current set
        // 1) issue LDGs for pair p+1
        if (p < 15) {
            ra0 = *reinterpret_cast<const float4*>(sbase  + (2*p+2)*32);
            ra1 = *reinterpret_cast<const float4*>(sbase2 + (2*p+2)*32);
            rb0 = *reinterpret_cast<const float4*>(sbase  + (2*p+3)*32);
            rb1 = *reinterpret_cast<const float4*>(sbase2 + (2*p+3)*32);
        }
        // 2) compute chunks 2p, 2p+1 from current set
        compute_chunk(xk + (2*s)*XKBUF,     ctrl_s, 2*p,     ks, eq, tg, acc);
        compute_chunk(xk + (2*s + 1)*XKBUF, ctrl_s, 2*p + 1, ks, eq, tg, acc);
        // 3) stage pair p+1 into the OTHER set
        if (p < 15) {
            float* b0 = xk + (2*(1 - s))*XKBUF;
            float* b1 = xk + (2*(1 - s) + 1)*XKBUF;
            const float* pa0 = reinterpret_cast<const float*>(&ra0);
            const float* pa1 = reinterpret_cast<const float*>(&ra1);
            const float* pb0 = reinterpret_cast<const float*>(&rb0);
            const float* pb1 = reinterpret_cast<const float*>(&rb1);
            #pragma unroll
            for (int j = 0; j < 4; j++) {
                b0[(s_kq*4 + j)*XKROW + s_tok0]      = pa0[j];
                b0[(s_kq*4 + j)*XKROW + s_tok0 + 64] = pa1[j];
                b1[(s_kq*4 + j)*XKROW + s_tok0]      = pb0[j];
                b1[(s_kq*4 + j)*XKROW + s_tok0 + 64] = pb1[j];
            }
        }
        __syncthreads();
    }

    // reduce over 4 k-slices via smem (reuse ctrl_s)
    ull* red = ctrl_s;
    #pragma unroll
    for (int i = 0; i < 4; i++)
        #pragma unroll
        for (int p = 0; p < 4; p++)
            red[(((size_t)(eq*4 + ks)*128) + (tg + 32*i))*4 + p] = acc[i][p];
    __syncthreads();

    #pragma unroll
    for (int j = 0; j < 4; j++) {
        int s = tid*4 + j;               // item = (tok, expert-pair)
        int tok = s >> 4, pr = s & 15;
        int peq = pr >> 2, pp = pr & 3;
        float lo = 0.f, hi = 0.f;
        #pragma unroll
        for (int k2 = 0; k2 < 4; k2++) {
            float a, b;
            unpack2(red[(((size_t)(peq*4 + k2)*128) + tok)*4 + pp], a, b);
            lo += a; hi += b;
        }
        int gt = tb*128 + tok;
        int b  = gt >> 12;
        int sg = gt & 4095;
        int g  = sg >> 2, t = sg & 3;
        float tbk = (float)t * (1e-6f / 3.0f);   // linspace(0,1e-6,4)[t]
        int row = (b*4 + t)*32 + 2*pr;
        g_logitsT[(size_t)row*1024 + g]     = lo + tbk;
        g_logitsT[(size_t)(row+1)*1024 + g] = hi + tbk;
    }
}

// ---------------------------------------------------------------------------
// K_sel: one block per (b,t,e) row: argmax + softmax denominator over 1024 g.
// ---------------------------------------------------------------------------
__global__ void __launch_bounds__(256, 8)
k_sel()
{
    __shared__ float rm[8];
    __shared__ int   rmi[8];
    __shared__ float rs[8];
    __shared__ float mfin;

    const int tid  = threadIdx.x;
    const int lane = tid & 31;
    const int wp   = tid >> 5;
    const float* L = g_logitsT + ((size_t)blockIdx.x << 10);

    float m = -3.4e38f; int mi = 0;
    #pragma unroll
    for (int j = 0; j < 4; j++) {
        int i = tid + j*256;
        float v = L[i];
        if (v > m) { m = v; mi = i; }
    }
    #pragma unroll
    for (int o = 16; o; o >>= 1) {
        float om = __shfl_down_sync(0xffffffffu, m, o);
        int   oi = __shfl_down_sync(0xffffffffu, mi, o);
        if (om > m || (om == m && oi < mi)) { m = om; mi = oi; }
    }
    if (lane == 0) { rm[wp] = m; rmi[wp] = mi; }
    __syncthreads();
    if (tid == 0) {
        #pragma unroll
        for (int w = 1; w < 8; w++) {
            if (rm[w] > m || (rm[w] == m && rmi[w] < mi)) { m = rm[w]; mi = rmi[w]; }
        }
        g_selg[blockIdx.x] = mi;
        mfin = m;
    }
    __syncthreads();
    m = mfin;

    float s = 0.f;
    #pragma unroll
    for (int j = 0; j < 4; j++) s += expf(L[tid + j*256] - m);
    #pragma unroll
    for (int o = 16; o; o >>= 1) s += __shfl_down_sync(0xffffffffu, s, o);
    if (lane == 0) rs[wp] = s;
    __syncthreads();
    if (tid == 0) {
        float tot = 0.f;
        #pragma unroll
        for (int w = 0; w < 8; w++) tot += rs[w];
        g_selp[blockIdx.x] = 1.0f / tot;
    }
}

// ---------------------------------------------------------------------------
// K2: up-proj + down-proj + scatter-add, split over 4 f-slices (R7 config).
// grid 512 = (b, e, fs) x 256 threads.
// ---------------------------------------------------------------------------
__global__ void __launch_bounds__(256, 4)
k_expert(const float* __restrict__ x, const float* __restrict__ f1,
         const float* __restrict__ bias, const float* __restrict__ f2,
         float* __restrict__ out)
{
    __shared__ float xs[4][DM];          // 16KB
    __shared__ float part[8][4][32];     // 4KB
    __shared__ float avs[4][32];
    __shared__ float Wsm[4][32];
    __shared__ int   sg[4];
    __shared__ float sp[4];

    const int tid  = threadIdx.x;
    const int lane = tid & 31;
    const int b  = blockIdx.x >> 7;
    const int e  = (blockIdx.x >> 2) & 31;
    const int fs = blockIdx.x & 3;

    if (tid < 4) {
        sg[tid] = g_selg[(b*4 + tid)*32 + e];
        sp[tid] = g_selp[(b*4 + tid)*32 + e];
    }
    __syncthreads();

    // --- load the 4 selected token rows into smem ---
    {
        const int ts = tid >> 6;
        const int gt = tid & 63;
        const float* xr = x + ((size_t)b*SEQ + sg[ts]*4 + ts) * DM;
        float4* dst = reinterpret_cast<float4*>(xs[ts]);
        const float4* src = reinterpret_cast<const float4*>(xr);
        #pragma unroll
        for (int i = 0; i < 4; i++) dst[gt + i*64] = src[gt + i*64];
    }
    __syncthreads();

    // --- up-projection for this block's 32 f's: warp w owns 128 d ---
    {
        const int w = tid >> 5;
        float a0 = 0.f, a1 = 0.f, a2 = 0.f, a3 = 0.f;
        const float* f1p = f1 + (size_t)(w*128)*(NEXP*FE) + e*FE + fs*32 + lane;
        const float* x0 = xs[0] + w*128;
        const float* x1 = xs[1] + w*128;
        const float* x2 = xs[2] + w*128;
        const float* x3 = xs[3] + w*128;
        #pragma unroll 16
        for (int d = 0; d < 128; d++) {
            float wv = f1p[(size_t)d * (NEXP*FE)];
            a0 += x0[d]*wv; a1 += x1[d]*wv; a2 += x2[d]*wv; a3 += x3[d]*wv;
        }
        part[w][0][lane] = a0; part[w][1][lane] = a1;
        part[w][2][lane] = a2; part[w][3][lane] = a3;
    }
    __syncthreads();

    if (tid < 128) {
        const int t = tid >> 5, f = tid & 31;
        float s = 0.f;
        #pragma unroll
        for (int w = 0; w < 8; w++) s += part[w][t][f];
        avs[t][f] = s;
    }
    __syncthreads();

    if (tid < 32) {
        const int f = tid;
        float av[4] = {avs[0][f], avs[1][f], avs[2][f], avs[3][f]};
        int   gg[4] = {sg[0], sg[1], sg[2], sg[3]};
        float pp[4] = {sp[0], sp[1], sp[2], sp[3]};
        float bi = bias[e*FE + fs*32 + f];
        #pragma unroll
        for (int t = 0; t < 4; t++) {
            float sum = bi;
            #pragma unroll
            for (int t2 = 0; t2 < 4; t2++)
                if (gg[t2] == gg[t]) sum += pp[t2] * av[t2];
            Wsm[t][f] = pp[t] * fmaxf(sum, 0.f);
        }
    }
    __syncthreads();

    // --- down-projection: thread owns 4 d' columns, 32 f rows ---
    {
        float o0[4] = {0,0,0,0}, o1[4] = {0,0,0,0};
        float o2[4] = {0,0,0,0}, o3[4] = {0,0,0,0};
        const float* f2p = f2 + (size_t)e*FE*DM + (size_t)(fs*32)*DM + tid*4;
        #pragma unroll 4
        for (int f = 0; f < 32; f++) {
            float4 v = *reinterpret_cast<const float4*>(f2p + (size_t)f*DM);
            float w0 = Wsm[0][f], w1 = Wsm[1][f], w2 = Wsm[2][f], w3 = Wsm[3][f];
            o0[0] += w0*v.x; o0[1] += w0*v.y; o0[2] += w0*v.z; o0[3] += w0*v.w;
            o1[0] += w1*v.x; o1[1] += w1*v.y; o1[2] += w1*v.z; o1[3] += w1*v.w;
            o2[0] += w2*v.x; o2[1] += w2*v.y; o2[2] += w2*v.z; o2[3] += w2*v.w;
            o3[0] += w3*v.x; o3[1] += w3*v.y; o3[2] += w3*v.z; o3[3] += w3*v.w;
        }
        float* ob = out + (size_t)b*SEQ*DM + tid*4;
        float* r0 = ob + (size_t)(sg[0]*4 + 0)*DM;
        float* r1 = ob + (size_t)(sg[1]*4 + 1)*DM;
        float* r2 = ob + (size_t)(sg[2]*4 + 2)*DM;
        float* r3 = ob + (size_t)(sg[3]*4 + 3)*DM;
        #pragma unroll
        for (int j = 0; j < 4; j++) atomicAdd(r0 + j, o0[j]);
        #pragma unroll
        for (int j = 0; j < 4; j++) atomicAdd(r1 + j, o1[j]);
        #pragma unroll
        for (int j = 0; j < 4; j++) atomicAdd(r2 + j, o2[j]);
        #pragma unroll
        for (int j = 0; j < 4; j++) atomicAdd(r3 + j, o3[j]);
    }
}

extern "C" void kernel_launch(void* const* d_in, const int* in_sizes, int n_in,
                              void* d_out, int out_size)
{
    const float* x    = (const float*)d_in[0];
    const float* ctrl = (const float*)d_in[1];
    const float* f1   = (const float*)d_in[2];
    const float* bias = (const float*)d_in[3];
    const float* f2   = (const float*)d_in[4];
    float* out = (float*)d_out;

    cudaFuncSetAttribute(k_logits, cudaFuncAttributeMaxDynamicSharedMemorySize, SMEM1);

    k_logits<<<128, 512, SMEM1>>>(x, ctrl, out);
    k_sel<<<BATCH*TT*NEXP, 256>>>();
    k_expert<<<BATCH*NEXP*4, 256>>>(x, f1, bias, f2, out);
}